// round 9
// baseline (speedup 1.0000x reference)
#include <cuda_runtime.h>
#include <cuda_bf16.h>

// BoundaryLoss fused kernel, v8: packed rings, no shuffles, base+imm loads.
//  - 128-thread block = full 512-px row width (4 cols/thread, float4)
//  - streams 20 rows (16 output + 4 halo), fully unrolled
//  - target bits packed 4-per-uint32; 5x5 box sum in exact parallel-byte
//    integer math (max 25 < 256); halo via float2 loads (no SHFL chains)
//  - all loads predicated with [base + immediate] addresses -> front-batchable
//  - packed rings: 5 (hsum) + 2 (center) + few regs -> deep MLP headroom
//  - pred loaded with __ldcs (single use, keep L2 for target halo reuse)
//  - 1024 blocks, all co-resident: one clean wave
//  - last-block finalize (threadfence + ticket), double accumulation

#define BATCH 32
#define HT 512
#define WD 512
#define ROWS 16                       // output rows per block
#define ITERS (ROWS + 4)              // 20 streamed rows
#define GRID_Y (HT / ROWS)            // 32
#define NBLK (GRID_Y * BATCH)         // 1024

__device__ double g_partials[NBLK];
__device__ unsigned int g_count;      // zero-init; reset by last block each launch

// 1.0f -> 1, 0.0f -> 0 via exponent bit (2 ALU ops, no F2I)
__device__ __forceinline__ unsigned int bit01(float v) {
    return (__float_as_uint(v) >> 23) & 1u;
}

__device__ __forceinline__ void bce_px(float x, unsigned int sbyte,
                                       unsigned int tbit, float& acc) {
    // boundary iff 1 <= boxsum <= 24 (exact integer byte)
    const float w = ((sbyte - 1u) < 24u) ? 5.0f : 1.0f;
    const float xt = tbit ? x : 0.0f;                    // t*x, t in {0,1}
    const float sp = __logf(1.0f + __expf(-fabsf(x))) + fmaxf(x, 0.0f);
    acc = fmaf(sp - xt, w, acc);
}

__global__ __launch_bounds__(128, 8)
void boundary_loss_kernel(const float* __restrict__ pred,
                          const float* __restrict__ target,
                          float* __restrict__ out) {
    const int tid  = threadIdx.x;        // 0..127
    const int lane = tid & 31;
    const int wid  = tid >> 5;
    const int c0   = tid * 4;            // this thread's 4 columns

    const int by = blockIdx.x;           // row-chunk (0..31)
    const int b  = blockIdx.y;           // batch     (0..31)

    const int r_base = by * ROWS - 2;    // first streamed row (may be -2)

    // Base pointers at (r_base, c0) / (by*ROWS, c0); deref only under predicate.
    const float* tbase = target + (size_t)b * HT * WD + (ptrdiff_t)r_base * WD + c0;
    const float* pbase = pred   + (size_t)b * HT * WD + (size_t)(by * ROWS) * WD + c0;

    const bool has_left  = (c0 > 0);          // false only for tid 0
    const bool has_right = (c0 + 4 < WD);     // false only for tid 127

    unsigned int hr[5];                  // packed horizontal 5-sums, rows j-4..j
    unsigned int cen[2];                 // packed target bits, 2-row delay ring
    float acc = 0.0f;

    #pragma unroll
    for (int j = 0; j < ITERS; j++) {
        const bool rv = (unsigned)(r_base + j) < (unsigned)HT;

        // 3 predicated loads, all [base + immediate] (j, WD compile-time)
        float4 t  = make_float4(0.f, 0.f, 0.f, 0.f);
        float2 tL = make_float2(0.f, 0.f);
        float2 tR = make_float2(0.f, 0.f);
        if (rv)              t  = *(const float4*)(tbase + j * WD);
        if (rv && has_left)  tL = *(const float2*)(tbase + j * WD - 2);
        if (rv && has_right) tR = *(const float2*)(tbase + j * WD + 4);

        // pack: tp bytes [t0,t1,t2,t3]; up has t-2@byte2,t-1@byte3; dn t+4@0,t+5@1
        const unsigned int tp = bit01(t.x) | (bit01(t.y) << 8) |
                                (bit01(t.z) << 16) | (bit01(t.w) << 24);
        const unsigned int up = (bit01(tL.x) << 16) | (bit01(tL.y) << 24);
        const unsigned int dn = bit01(tR.x) | (bit01(tR.y) << 8);

        // horizontal 5-sum per byte (cols c-2..c+2 for the 4 columns)
        const unsigned int vm2 = __byte_perm(up, tp, 0x5432); // [t-2,t-1,t0,t1]
        const unsigned int vm1 = __byte_perm(up, tp, 0x6543); // [t-1,t0,t1,t2]
        const unsigned int vp1 = __byte_perm(tp, dn, 0x4321); // [t1,t2,t3,t4]
        const unsigned int vp2 = __byte_perm(tp, dn, 0x5432); // [t2,t3,t4,t5]
        hr[j % 5] = (vm2 + vm1) + tp + (vp1 + vp2);           // bytes <= 5

        // center target bits, needed 2 iterations later
        const unsigned int tc = cen[j & 1];
        cen[j & 1] = tp;

        if (j >= 4) {
            // fresh packed vertical 5-sum (no cross-iteration recurrence)
            const unsigned int s = (hr[0] + hr[1]) + hr[2] + (hr[3] + hr[4]);

            const float4 p = __ldcs((const float4*)(pbase + (j - 4) * WD));

            bce_px(p.x,  s         & 255u, tc & 0x00000001u, acc);
            bce_px(p.y, (s >> 8)   & 255u, tc & 0x00000100u, acc);
            bce_px(p.z, (s >> 16)  & 255u, tc & 0x00010000u, acc);
            bce_px(p.w,  s >> 24,          tc & 0x01000000u, acc);
        }
    }

    // ---- block reduction: warp fp32 -> smem -> double ----
    #pragma unroll
    for (int off = 16; off > 0; off >>= 1)
        acc += __shfl_xor_sync(0xFFFFFFFFu, acc, off);

    __shared__ float s_warp[4];
    __shared__ unsigned int s_islast;
    if (lane == 0) s_warp[wid] = acc;
    __syncthreads();

    if (tid == 0) {
        double d = (double)s_warp[0] + (double)s_warp[1]
                 + (double)s_warp[2] + (double)s_warp[3];
        const int bid = blockIdx.x + GRID_Y * blockIdx.y;
        g_partials[bid] = d;
        __threadfence();
        const unsigned int ticket = atomicAdd(&g_count, 1u);
        s_islast = (ticket == NBLK - 1) ? 1u : 0u;
    }
    __syncthreads();

    // ---- last block finalizes ----
    if (s_islast) {
        const volatile double* vp = (const volatile double*)g_partials;
        double d = 0.0;
        #pragma unroll
        for (int i = 0; i < NBLK / 128; i++)
            d += vp[tid + i * 128];

        #pragma unroll
        for (int off = 16; off > 0; off >>= 1)
            d += __shfl_xor_sync(0xFFFFFFFFu, d, off);

        __shared__ double s_dw[4];
        if (lane == 0) s_dw[wid] = d;
        __syncthreads();

        if (tid == 0) {
            const double tot = s_dw[0] + s_dw[1] + s_dw[2] + s_dw[3];
            out[0] = (float)(tot / ((double)BATCH * HT * WD));
            g_count = 0;     // reset for next graph replay
        }
    }
}

extern "C" void kernel_launch(void* const* d_in, const int* in_sizes, int n_in,
                              void* d_out, int out_size) {
    const float* pred   = (const float*)d_in[0];
    const float* target = (const float*)d_in[1];
    float* out = (float*)d_out;

    dim3 grid(GRID_Y, BATCH);    // 32 x 32 = 1024 blocks, single clean wave
    boundary_loss_kernel<<<grid, 128>>>(pred, target, out);
}

// round 10
// speedup vs baseline: 1.0270x; 1.0270x over previous
#include <cuda_runtime.h>
#include <cuda_bf16.h>

// BoundaryLoss fused kernel, v9: 2 cols/thread, 2048 blocks, one full wave.
//  - tile = 256 cols x 16 rows, 128 threads, 2 cols/thread (float2 loads)
//  - grid 2x32x32 = 2048 blocks = 262K threads (87% occ), single wave at
//    16 blocks/SM (__launch_bounds__(128,16) -> 32-reg budget)
//  - streams 20 rows; horizontal 5-sum from 3 adjacent float2 loads
//    (5 FADD w/ CSE); vertical = fresh 5-ring re-sum (8 FADD)
//  - center target re-loaded from L1 (same addr as 2 iters ago) - no ring
//  - halo rows/cols overlap between co-resident blocks -> L2 hits, not DRAM
//  - last-block finalize (threadfence + ticket), double accumulation

#define BATCH 32
#define HT 512
#define WD 512
#define ROWS 16                       // output rows per block
#define ITERS (ROWS + 4)              // 20 streamed rows
#define TXC 256                       // cols per block
#define GRID_X (WD / TXC)             // 2
#define GRID_Y (HT / ROWS)            // 32
#define NBLK (GRID_X * GRID_Y * BATCH)  // 2048

__device__ double g_partials[NBLK];
__device__ unsigned int g_count;      // zero-init; reset by last block each launch

__device__ __forceinline__ void bce_w(float x, float t, float s, float& acc) {
    // weight: 5 inside boundary band (0 < boxsum < 25), else 1 (boxsum exact int)
    const float w = (s > 0.5f && s < 24.5f) ? 5.0f : 1.0f;
    // BCE(sigmoid(x), t) = softplus(x) - t*x; stable fast-math softplus
    const float sp = __logf(1.0f + __expf(-fabsf(x))) + fmaxf(x, 0.0f);
    acc = fmaf(fmaf(-x, t, sp), w, acc);
}

__global__ __launch_bounds__(128, 16)
void boundary_loss_kernel(const float* __restrict__ pred,
                          const float* __restrict__ target,
                          float* __restrict__ out) {
    const int tid  = threadIdx.x;        // 0..127
    const int lane = tid & 31;
    const int wid  = tid >> 5;

    const int bx = blockIdx.x;           // col-half  (0..1)
    const int by = blockIdx.y;           // row-chunk (0..31)
    const int b  = blockIdx.z;           // batch     (0..31)

    const int c0 = bx * TXC + tid * 2;   // this thread's 2 columns
    const int r_base = by * ROWS - 2;    // first streamed row (may be -2)

    // Base pointers at (r_base, c0) / (by*ROWS, c0); deref only under predicate.
    const float* tbase = target + (size_t)b * HT * WD + (ptrdiff_t)r_base * WD + c0;
    const float* pbase = pred   + (size_t)b * HT * WD + (size_t)(by * ROWS) * WD + c0;

    const bool has_left  = (c0 > 0);          // false only at image col 0
    const bool has_right = (c0 + 2 < WD);     // false only at image col 510

    float2 hr[5];                        // horizontal 5-sums, rows j-4..j
    float acc = 0.0f;

    #pragma unroll
    for (int j = 0; j < ITERS; j++) {
        const bool rv = (unsigned)(r_base + j) < (unsigned)HT;

        // 3 adjacent float2 loads cover window cols c0-2 .. c0+3
        float2 tL = make_float2(0.f, 0.f);
        float2 t  = make_float2(0.f, 0.f);
        float2 tR = make_float2(0.f, 0.f);
        if (rv)              t  = *(const float2*)(tbase + j * WD);
        if (rv && has_left)  tL = *(const float2*)(tbase + j * WD - 2);
        if (rv && has_right) tR = *(const float2*)(tbase + j * WD + 2);

        // horizontal 5-sums for the 2 columns (CSE: 5 FADD)
        const float m = tL.y + t.x + t.y + tR.x;
        float2 h;
        h.x = tL.x + m;
        h.y = m + tR.y;
        hr[j % 5] = h;

        if (j >= 4) {
            // fresh vertical 5-sum (exact small-int fp)
            const float sx = (hr[0].x + hr[1].x) + hr[2].x + (hr[3].x + hr[4].x);
            const float sy = (hr[0].y + hr[1].y) + hr[2].y + (hr[3].y + hr[4].y);

            // center target: same address as the t of 2 iterations ago -> L1 hit
            const float2 tc = *(const float2*)(tbase + (j - 2) * WD);
            const float2 p  = *(const float2*)(pbase + (j - 4) * WD);

            bce_w(p.x, tc.x, sx, acc);
            bce_w(p.y, tc.y, sy, acc);
        }
    }

    // ---- block reduction: warp fp32 -> smem -> double ----
    #pragma unroll
    for (int off = 16; off > 0; off >>= 1)
        acc += __shfl_xor_sync(0xFFFFFFFFu, acc, off);

    __shared__ float s_warp[4];
    __shared__ unsigned int s_islast;
    if (lane == 0) s_warp[wid] = acc;
    __syncthreads();

    if (tid == 0) {
        double d = (double)s_warp[0] + (double)s_warp[1]
                 + (double)s_warp[2] + (double)s_warp[3];
        const int bid = blockIdx.x + GRID_X * (blockIdx.y + GRID_Y * blockIdx.z);
        g_partials[bid] = d;
        __threadfence();
        const unsigned int ticket = atomicAdd(&g_count, 1u);
        s_islast = (ticket == NBLK - 1) ? 1u : 0u;
    }
    __syncthreads();

    // ---- last block finalizes ----
    if (s_islast) {
        const volatile double* vp = (const volatile double*)g_partials;
        double d = 0.0;
        #pragma unroll
        for (int i = 0; i < NBLK / 128; i++)
            d += vp[tid + i * 128];

        #pragma unroll
        for (int off = 16; off > 0; off >>= 1)
            d += __shfl_xor_sync(0xFFFFFFFFu, d, off);

        __shared__ double s_dw[4];
        if (lane == 0) s_dw[wid] = d;
        __syncthreads();

        if (tid == 0) {
            const double tot = s_dw[0] + s_dw[1] + s_dw[2] + s_dw[3];
            out[0] = (float)(tot / ((double)BATCH * HT * WD));
            g_count = 0;     // reset for next graph replay
        }
    }
}

extern "C" void kernel_launch(void* const* d_in, const int* in_sizes, int n_in,
                              void* d_out, int out_size) {
    const float* pred   = (const float*)d_in[0];
    const float* target = (const float*)d_in[1];
    float* out = (float*)d_out;

    dim3 grid(GRID_X, GRID_Y, BATCH);   // 2 x 32 x 32 = 2048 blocks, one wave
    boundary_loss_kernel<<<grid, 128>>>(pred, target, out);
}